// round 5
// baseline (speedup 1.0000x reference)
#include <cuda_runtime.h>
#include <cuda_bf16.h>
#include <cstdint>

#define DIM      4096
#define NUMEL    (DIM*DIM)
#define KTOT     8388608u
#define KB_TOT   2048
#define NBINS    8192
#define CAP      12288
#define SEL_SMEM  (CAP*8 + 4096*4)

#if defined(__CUDA_ARCH_FEAT_SM103_ALL) || defined(__CUDA_ARCH_FEAT_SM100_ALL)
#define HAS_TC 1
#else
#define HAS_TC 0
#endif

// ---- tcgen05 path config ----
#define TM       128
#define TN       256
#define NSTAGE_T 192
#define NBUF_T   3
#define A_BYTES  (TM*128)
#define STG_T    (A_BYTES + TN*128)
#define TC_SMEM  (2048 + NBUF_T*STG_T)

// ---- fallback path config ----
#define FM       256
#define FN       128
#define NSTAGE_F 384
#define STG_F    24576
#define FB_SMEM  (1024 + 4*STG_F)

static constexpr uint32_t IDESC =
    (1u<<4) | (1u<<7) | (1u<<10) | ((TN/8)<<17) | ((TM/16)<<24);
static constexpr uint64_t DESC_BASE =
    (uint64_t(2)<<61) | (uint64_t(1)<<46) | (uint64_t(64)<<32) | (uint64_t(1)<<16);
#define SWZ(off) ((off) ^ (((off)>>3)&0x70))
#define MKDESC(a) (DESC_BASE | ((uint64_t)((a)>>4) & 0x3FFF))
#define FOFF(r,c) ((uint32_t)(((r)>>1)*128 + (((((r)&1)<<2)|(c)) ^ (((r)>>1)&7))*16))

__device__ __nv_bfloat16 g_A0[(size_t)DIM*8192];
__device__ __nv_bfloat16 g_A1[(size_t)DIM*8192];
__device__ __nv_bfloat16 g_Wm[(size_t)DIM*8192];
__device__ unsigned int g_hist[NBINS];
__device__ int   g_binstar, g_cbefore, g_cand_cnt;
__device__ float g_cand_val[CAP];
__device__ int   g_cand_idx[CAP];
__device__ float g_tval;
__device__ int   g_tidx;
__device__ float g_bm[DIM];

__device__ __forceinline__ uint32_t smem_u32(const void* p) {
    uint32_t a;
    asm("{ .reg .u64 t; cvta.to.shared.u64 t, %1; cvt.u32.u64 %0, t; }" : "=r"(a) : "l"(p));
    return a;
}
__device__ __forceinline__ void cp16(uint32_t dst, const void* src) {
    asm volatile("cp.async.cg.shared.global [%0], [%1], 16;" :: "r"(dst), "l"(src));
}
#define CP_COMMIT() asm volatile("cp.async.commit_group;" ::: "memory")
#define CP_WAIT(n)  asm volatile("cp.async.wait_group %0;" :: "n"(n) : "memory")

__device__ __forceinline__ int qval(float v) {
    int q = (int)(v * 33554432.0f);
    return q < 0 ? 0 : (q > 33554431 ? 33554431 : q);
}
__device__ __forceinline__ void split_bf16(float v, unsigned short& h, unsigned short& l) {
    __nv_bfloat16 hb = __float2bfloat16(v);
    __nv_bfloat16 lb = __float2bfloat16(v - __bfloat162float(hb));
    h = __bfloat16_as_ushort(hb); l = __bfloat16_as_ushort(lb);
}

// ---------------- masking pipeline ----------------
__global__ void clear_kernel() {
    for (int i = threadIdx.x; i < NBINS; i += 1024) g_hist[i] = 0;
    if (threadIdx.x == 0) g_cand_cnt = 0;
}

__global__ void hist_kernel(const float4* __restrict__ M4) {
    __shared__ unsigned int h[NBINS];
    for (int i = threadIdx.x; i < NBINS; i += 256) h[i] = 0;
    __syncthreads();
    int stride = gridDim.x * blockDim.x;
    for (int i = blockIdx.x*blockDim.x + threadIdx.x; i < NUMEL/4; i += stride) {
        float4 v = M4[i];
        atomicAdd(&h[qval(v.x)>>12], 1u); atomicAdd(&h[qval(v.y)>>12], 1u);
        atomicAdd(&h[qval(v.z)>>12], 1u); atomicAdd(&h[qval(v.w)>>12], 1u);
    }
    __syncthreads();
    for (int i = threadIdx.x; i < NBINS; i += 256)
        if (h[i]) atomicAdd(&g_hist[i], h[i]);
}

__global__ void scan_kernel() {
    __shared__ unsigned int part[1024], base[1024];
    int t = threadIdx.x;
    unsigned int s = 0;
    for (int j = 0; j < 8; j++) s += g_hist[t*8+j];
    part[t] = s;
    __syncthreads();
    if (t == 0) { unsigned int r = 0; for (int i = 0; i < 1024; i++) { base[i] = r; r += part[i]; } }
    __syncthreads();
    unsigned int run = base[t];
    for (int j = 0; j < 8; j++) {
        unsigned int c = g_hist[t*8+j];
        if (run < KTOT && run + c >= KTOT) { g_binstar = t*8+j; g_cbefore = (int)run; }
        run += c;
    }
}

__global__ void gather_kernel(const float4* __restrict__ M4) {
    int bstar = g_binstar;
    int stride = gridDim.x * blockDim.x;
    for (int i = blockIdx.x*blockDim.x + threadIdx.x; i < NUMEL/4; i += stride) {
        float4 v = M4[i];
        float vv[4] = {v.x, v.y, v.z, v.w};
        #pragma unroll
        for (int j = 0; j < 4; j++)
            if ((qval(vv[j])>>12) == bstar) {
                int p = atomicAdd(&g_cand_cnt, 1);
                if (p < CAP) { g_cand_val[p] = vv[j]; g_cand_idx[p] = i*4+j; }
            }
    }
}

__global__ void select_kernel() {
    extern __shared__ char sm[];
    float* sv = (float*)sm;
    int* si = (int*)(sm + CAP*4);
    unsigned int* sh = (unsigned int*)(sm + CAP*8);
    __shared__ unsigned int spart[1024], sbas[1024];
    __shared__ int s_b2, s_need2;
    int t = threadIdx.x;
    int c = g_cand_cnt; if (c > CAP) c = CAP;
    int need = (int)KTOT - g_cbefore;
    for (int i = t; i < c; i += 1024) { sv[i] = g_cand_val[i]; si[i] = g_cand_idx[i]; }
    for (int i = t; i < 4096; i += 1024) sh[i] = 0;
    __syncthreads();
    for (int i = t; i < c; i += 1024) atomicAdd(&sh[qval(sv[i]) & 4095], 1u);
    __syncthreads();
    { unsigned int s = 0; for (int j = 0; j < 4; j++) s += sh[t*4+j]; spart[t] = s; }
    __syncthreads();
    if (t == 0) { unsigned int r = 0; for (int i = 0; i < 1024; i++) { sbas[i] = r; r += spart[i]; } }
    __syncthreads();
    { unsigned int run = sbas[t];
      for (int j = 0; j < 4; j++) {
          unsigned int cc = sh[t*4+j];
          if (run < (unsigned)need && run + cc >= (unsigned)need) { s_b2 = t*4+j; s_need2 = need - (int)run; }
          run += cc;
      } }
    __syncthreads();
    int b2 = s_b2, need2 = s_need2;
    for (int j = t; j < c; j += 1024) {
        float vj = sv[j];
        if ((qval(vj) & 4095) != b2) continue;
        int ij = si[j], cnt = 0;
        for (int i = 0; i < c; i++) {
            float v = sv[i];
            if ((qval(v) & 4095) != b2) continue;
            cnt += (v < vj) || (v == vj && si[i] < ij);
        }
        if (cnt == need2 - 1) { g_tval = vj; g_tidx = ij; }
    }
}

__global__ void biasmask_kernel(const float* __restrict__ b, const float* __restrict__ mb) {
    __shared__ float svv[DIM];
    int t = threadIdx.x, j = blockIdx.x*256 + t;
    for (int i = t; i < DIM; i += 256) svv[i] = mb[i];
    __syncthreads();
    float vj = svv[j];
    int cnt = 0;
    for (int i = 0; i < DIM; i++) { float v = svv[i]; cnt += (v < vj) || (v == vj && i < j); }
    g_bm[j] = (cnt < KB_TOT) ? 0.0f : b[j];
}

__global__ void maskconv_kernel(const float4* __restrict__ W4, const float4* __restrict__ M4) {
    float tv = g_tval; int ti = g_tidx;
    int stride = gridDim.x * blockDim.x;
    unsigned short* Wo = (unsigned short*)g_Wm;
    for (int i = blockIdx.x*blockDim.x + threadIdx.x; i < NUMEL/4; i += stride) {
        float4 w = W4[i]; float4 m = M4[i];
        float wv[4] = {w.x, w.y, w.z, w.w};
        float mv[4] = {m.x, m.y, m.z, m.w};
        int e0 = i*4;
        unsigned short hh[4], ll[4];
        #pragma unroll
        for (int j = 0; j < 4; j++) {
            bool z = (mv[j] < tv) || (mv[j] == tv && (e0+j) <= ti);
            split_bf16(z ? 0.0f : wv[j], hh[j], ll[j]);
        }
        size_t base = (size_t)(e0>>12)*8192 + (e0 & 4095);
        *(ushort4*)(Wo + base)        = make_ushort4(hh[0],hh[1],hh[2],hh[3]);
        *(ushort4*)(Wo + base + 4096) = make_ushort4(ll[0],ll[1],ll[2],ll[3]);
    }
}

__global__ void split_x_kernel(const float4* __restrict__ x4) {
    int stride = gridDim.x * blockDim.x;
    unsigned short* Ao = (unsigned short*)g_A0;
    for (int i = blockIdx.x*blockDim.x + threadIdx.x; i < NUMEL/4; i += stride) {
        float4 v = x4[i];
        float vv[4] = {v.x, v.y, v.z, v.w};
        unsigned short hh[4], ll[4];
        #pragma unroll
        for (int j = 0; j < 4; j++) split_bf16(vv[j], hh[j], ll[j]);
        int e0 = i*4;
        size_t base = (size_t)(e0>>12)*8192 + (e0 & 4095);
        *(ushort4*)(Ao + base)        = make_ushort4(hh[0],hh[1],hh[2],hh[3]);
        *(ushort4*)(Ao + base + 4096) = make_ushort4(ll[0],ll[1],ll[2],ll[3]);
    }
}

// ---------------- tcgen05 GEMM (sm_103a-only, guarded) ----------------
template <bool FINAL>
__global__ void __launch_bounds__(256, 1) gemm_tc(
    const __nv_bfloat16* __restrict__ A,
    unsigned short* __restrict__ outb, float* __restrict__ outf)
{
#if HAS_TC
    extern __shared__ char smem[];
    uint32_t sb = smem_u32(smem);
    float* sbias = (float*)(smem + 64);
    int tid = threadIdx.x, wid = tid >> 5, lane = tid & 31;
    int tn = blockIdx.x, tm = blockIdx.y;

    if (tid == 0) {
        asm volatile("mbarrier.init.shared.b64 [%0], 1;" :: "r"(sb+16) : "memory");
        asm volatile("mbarrier.init.shared.b64 [%0], 1;" :: "r"(sb+24) : "memory");
        asm volatile("mbarrier.init.shared.b64 [%0], 1;" :: "r"(sb+32) : "memory");
    }
    if (wid == 0) {
        asm volatile("tcgen05.alloc.cta_group::1.sync.aligned.shared::cta.b32 [%0], %1;"
            :: "r"(sb), "r"((uint32_t)TN) : "memory");
        asm volatile("tcgen05.relinquish_alloc_permit.cta_group::1.sync.aligned;");
    }
    sbias[tid] = g_bm[tn*TN + tid];
    __syncthreads();
    uint32_t tbase;
    asm volatile("ld.shared.b32 %0, [%1];" : "=r"(tbase) : "r"(sb));

    const char* Ab = (const char*)A;
    const char* Wb = (const char*)g_Wm;

    #define TLOAD(s) do { \
        int seg_ = (s) >> 6, kk_ = ((s) & 63) << 6; \
        int aoff_ = (seg_ == 1 ? 4096 : 0) + kk_; \
        int boff_ = (seg_ == 2 ? 4096 : 0) + kk_; \
        uint32_t stg_ = sb + 2048 + ((s) % NBUF_T) * STG_T; \
        for (int u = tid; u < 3072; u += 256) { \
            if (u < 1024) { \
                int r_ = u >> 3, c_ = u & 7; \
                uint32_t off_ = (uint32_t)(r_*128 + c_*16); \
                cp16(stg_ + SWZ(off_), Ab + (((size_t)(tm*TM + r_))*8192 + aoff_ + c_*8)*2); \
            } else { \
                int v_ = u - 1024, r_ = v_ >> 3, c_ = v_ & 7; \
                uint32_t off_ = (uint32_t)(r_*128 + c_*16); \
                cp16(stg_ + A_BYTES + SWZ(off_), Wb + (((size_t)(tn*TN + r_))*8192 + boff_ + c_*8)*2); \
            } \
        } \
        CP_COMMIT(); \
    } while (0)

    TLOAD(0); TLOAD(1); TLOAD(2);

    for (int s = 0; s < NSTAGE_T; s++) {
        if (s < NSTAGE_T-2)       { CP_WAIT(2); }
        else if (s == NSTAGE_T-2) { CP_WAIT(1); }
        else                      { CP_WAIT(0); }
        __syncthreads();
        uint32_t ep;
        asm volatile("{\n\t.reg .pred P;\n\telect.sync _|P, 0xFFFFFFFF;\n\tselp.b32 %0,1,0,P;\n\t}" : "=r"(ep));
        if (wid == 0 && ep) {
            asm volatile("fence.proxy.async.shared::cta;" ::: "memory");
            uint32_t stg = sb + 2048 + (s % NBUF_T) * STG_T;
            uint64_t ad = MKDESC(stg), bd = MKDESC(stg + A_BYTES);
            #pragma unroll
            for (int k = 0; k < 4; k++) {
                uint32_t en = ((s | k) != 0);
                asm volatile("{\n\t.reg .pred p;\n\tsetp.ne.u32 p, %5, 0;\n\t"
                    "tcgen05.mma.cta_group::1.kind::f16 [%0], %1, %2, %3, {%4,%4,%4,%4}, p;\n\t}"
                    :: "r"(tbase), "l"(ad + k*2), "l"(bd + k*2), "r"(IDESC), "r"(0u), "r"(en) : "memory");
            }
            asm volatile("tcgen05.commit.cta_group::1.mbarrier::arrive::one.shared::cluster.b64 [%0];"
                :: "r"(sb + 16 + (s % NBUF_T)*8) : "memory");
        }
        if (s + NBUF_T < NSTAGE_T) {
            uint32_t mb = sb + 16 + (s % NBUF_T)*8, par = (uint32_t)((s / NBUF_T) & 1);
            asm volatile("{\n\t.reg .pred P;\n\tWL_%=:\n\t"
                "mbarrier.try_wait.parity.acquire.cta.shared::cta.b64 P, [%0], %1, 0x989680;\n\t"
                "@P bra.uni WD_%=;\n\tbra.uni WL_%=;\n\tWD_%=:\n\t}" :: "r"(mb), "r"(par) : "memory");
            TLOAD(s + NBUF_T);
        }
    }
    {
        uint32_t mb = sb + 16 + ((NSTAGE_T-1) % NBUF_T)*8, par = (uint32_t)(((NSTAGE_T-1) / NBUF_T) & 1);
        asm volatile("{\n\t.reg .pred P;\n\tWL_%=:\n\t"
            "mbarrier.try_wait.parity.acquire.cta.shared::cta.b64 P, [%0], %1, 0x989680;\n\t"
            "@P bra.uni WD_%=;\n\tbra.uni WL_%=;\n\tWD_%=:\n\t}" :: "r"(mb), "r"(par) : "memory");
    }
    __syncthreads();
    asm volatile("tcgen05.fence::after_thread_sync;" ::: "memory");

    if (wid < 4) {
        int m = tm*TM + wid*32 + lane;
        #pragma unroll 1
        for (int g = 0; g < 8; g++) {
            uint32_t r[32];
            asm volatile("tcgen05.ld.sync.aligned.32x32b.x32.b32 "
                "{%0,%1,%2,%3,%4,%5,%6,%7,%8,%9,%10,%11,%12,%13,%14,%15,"
                "%16,%17,%18,%19,%20,%21,%22,%23,%24,%25,%26,%27,%28,%29,%30,%31}, [%32];"
                : "=r"(r[0]),"=r"(r[1]),"=r"(r[2]),"=r"(r[3]),"=r"(r[4]),"=r"(r[5]),"=r"(r[6]),"=r"(r[7]),
                  "=r"(r[8]),"=r"(r[9]),"=r"(r[10]),"=r"(r[11]),"=r"(r[12]),"=r"(r[13]),"=r"(r[14]),"=r"(r[15]),
                  "=r"(r[16]),"=r"(r[17]),"=r"(r[18]),"=r"(r[19]),"=r"(r[20]),"=r"(r[21]),"=r"(r[22]),"=r"(r[23]),
                  "=r"(r[24]),"=r"(r[25]),"=r"(r[26]),"=r"(r[27]),"=r"(r[28]),"=r"(r[29]),"=r"(r[30]),"=r"(r[31])
                : "r"(tbase + g*32));
            asm volatile("tcgen05.wait::ld.sync.aligned;" ::: "memory");
            if (!FINAL) {
                #pragma unroll
                for (int q = 0; q < 8; q++) {
                    unsigned short hh[4], ll[4];
                    #pragma unroll
                    for (int j = 0; j < 4; j++) {
                        float v = __uint_as_float(r[q*4+j]) + sbias[g*32 + q*4 + j];
                        split_bf16(fmaxf(v, 0.0f), hh[j], ll[j]);
                    }
                    size_t base = (size_t)m*8192 + tn*TN + g*32 + q*4;
                    *(ushort4*)(outb + base)        = make_ushort4(hh[0],hh[1],hh[2],hh[3]);
                    *(ushort4*)(outb + base + 4096) = make_ushort4(ll[0],ll[1],ll[2],ll[3]);
                }
            } else {
                #pragma unroll
                for (int q = 0; q < 8; q++) {
                    float4 v;
                    v.x = __uint_as_float(r[q*4+0]) + sbias[g*32+q*4+0];
                    v.y = __uint_as_float(r[q*4+1]) + sbias[g*32+q*4+1];
                    v.z = __uint_as_float(r[q*4+2]) + sbias[g*32+q*4+2];
                    v.w = __uint_as_float(r[q*4+3]) + sbias[g*32+q*4+3];
                    *(float4*)(outf + (size_t)m*4096 + tn*TN + g*32 + q*4) = v;
                }
            }
        }
    }
    __syncthreads();
    if (wid == 0)
        asm volatile("tcgen05.dealloc.cta_group::1.sync.aligned.b32 %0, %1;" :: "r"(tbase), "r"((uint32_t)TN));
#endif
}

// ---------------- fallback GEMM: mma.sync bf16 (plain sm_103) ----------------
#define LDSM4(r, a) asm volatile("ldmatrix.sync.aligned.m8n8.x4.shared.b16 {%0,%1,%2,%3}, [%4];" \
    : "=r"((r)[0]),"=r"((r)[1]),"=r"((r)[2]),"=r"((r)[3]) : "r"(a))
#define MMA16816(acc, a, b0, b1) asm volatile( \
    "mma.sync.aligned.m16n8k16.row.col.f32.bf16.bf16.f32 {%0,%1,%2,%3},{%4,%5,%6,%7},{%8,%9},{%0,%1,%2,%3};" \
    : "+f"((acc)[0]),"+f"((acc)[1]),"+f"((acc)[2]),"+f"((acc)[3]) \
    : "r"((a)[0]),"r"((a)[1]),"r"((a)[2]),"r"((a)[3]),"r"(b0),"r"(b1))

template <bool FINAL>
__global__ void __launch_bounds__(512, 1) gemm_fb(
    const __nv_bfloat16* __restrict__ A,
    unsigned short* __restrict__ outb, float* __restrict__ outf)
{
#if !HAS_TC
    extern __shared__ char smem[];
    uint32_t sb = smem_u32(smem);
    float* sbias = (float*)smem;
    int tid = threadIdx.x, wid = tid >> 5, lane = tid & 31;
    int mw = wid >> 2, nw = wid & 3;
    int tn = blockIdx.x, tm = blockIdx.y;
    if (tid < FN) sbias[tid] = g_bm[tn*FN + tid];

    const char* Ab = (const char*)A;
    const char* Wb = (const char*)g_Wm;

    float acc[4][4][4];
    #pragma unroll
    for (int i = 0; i < 4; i++)
        #pragma unroll
        for (int j = 0; j < 4; j++)
            #pragma unroll
            for (int k = 0; k < 4; k++) acc[i][j][k] = 0.f;

    #define FLOAD(s) do { \
        int seg_ = (s) >> 7, kk_ = ((s) & 127) << 5; \
        int aoff_ = (seg_ == 1 ? 4096 : 0) + kk_; \
        int boff_ = (seg_ == 2 ? 4096 : 0) + kk_; \
        uint32_t stg_ = sb + 1024 + ((s) & 3) * STG_F; \
        for (int u = tid; u < 1536; u += 512) { \
            if (u < 1024) { int r_ = u >> 2, c_ = u & 3; \
                cp16(stg_ + FOFF(r_, c_), Ab + (((size_t)(tm*FM + r_))*8192 + aoff_ + c_*8)*2); \
            } else { int v_ = u - 1024, r_ = v_ >> 2, c_ = v_ & 3; \
                cp16(stg_ + 16384 + FOFF(r_, c_), Wb + (((size_t)(tn*FN + r_))*8192 + boff_ + c_*8)*2); } \
        } \
        CP_COMMIT(); \
    } while (0)

    FLOAD(0); FLOAD(1); FLOAD(2);

    int rA = mw*64 + (lane & 15);
    int rB = nw*32 + (lane & 15);
    int chh = lane >> 4;

    for (int s = 0; s < NSTAGE_F; s++) {
        CP_WAIT(2);
        __syncthreads();
        if (s + 3 < NSTAGE_F) FLOAD(s + 3);
        uint32_t astg = sb + 1024 + (s & 3) * STG_F;
        uint32_t bstg = astg + 16384;
        #pragma unroll
        for (int ks = 0; ks < 2; ks++) {
            int ch = ks*2 + chh;
            uint32_t a[4][4], b[2][4];
            #pragma unroll
            for (int mt = 0; mt < 4; mt++) LDSM4(a[mt], astg + FOFF(rA + mt*16, ch));
            #pragma unroll
            for (int nt = 0; nt < 2; nt++) LDSM4(b[nt], bstg + FOFF(rB + nt*16, ch));
            #pragma unroll
            for (int mt = 0; mt < 4; mt++)
                #pragma unroll
                for (int nt = 0; nt < 2; nt++)
                    #pragma unroll
                    for (int h = 0; h < 2; h++)
                        MMA16816(acc[mt][nt*2+h], a[mt], b[nt][h], b[nt][h+2]);
        }
        __syncthreads();
    }

    int mwb = tm*FM + mw*64;
    #pragma unroll
    for (int mt = 0; mt < 4; mt++)
        #pragma unroll
        for (int nt = 0; nt < 2; nt++)
            #pragma unroll
            for (int h = 0; h < 2; h++) {
                float* c = acc[mt][nt*2+h];
                int m0 = mwb + mt*16 + (lane >> 2);
                int nl = nw*32 + nt*16 + h*8 + (lane & 3)*2;
                int ng = tn*FN + nl;
                float b0 = sbias[nl], b1 = sbias[nl+1];
                #pragma unroll
                for (int rr = 0; rr < 2; rr++) {
                    int m = m0 + rr*8;
                    float v0 = c[rr*2+0] + b0, v1 = c[rr*2+1] + b1;
                    if (!FINAL) {
                        unsigned short h0, l0, h1, l1;
                        split_bf16(fmaxf(v0, 0.f), h0, l0);
                        split_bf16(fmaxf(v1, 0.f), h1, l1);
                        size_t base = (size_t)m*8192 + ng;
                        *(unsigned int*)(outb + base)        = (unsigned int)h0 | ((unsigned int)h1 << 16);
                        *(unsigned int*)(outb + base + 4096) = (unsigned int)l0 | ((unsigned int)l1 << 16);
                    } else {
                        *(float2*)(outf + (size_t)m*4096 + ng) = make_float2(v0, v1);
                    }
                }
            }
#endif
}

// ---------------- launch ----------------
extern "C" void kernel_launch(void* const* d_in, const int* in_sizes, int n_in,
                              void* d_out, int out_size) {
    (void)in_sizes; (void)n_in; (void)out_size;
    cudaFuncSetAttribute(select_kernel, cudaFuncAttributeMaxDynamicSharedMemorySize, SEL_SMEM);
    cudaFuncSetAttribute(gemm_tc<false>, cudaFuncAttributeMaxDynamicSharedMemorySize, TC_SMEM);
    cudaFuncSetAttribute(gemm_tc<true>,  cudaFuncAttributeMaxDynamicSharedMemorySize, TC_SMEM);
    cudaFuncSetAttribute(gemm_fb<false>, cudaFuncAttributeMaxDynamicSharedMemorySize, FB_SMEM);
    cudaFuncSetAttribute(gemm_fb<true>,  cudaFuncAttributeMaxDynamicSharedMemorySize, FB_SMEM);

    void *pA0, *pA1;
    cudaGetSymbolAddress(&pA0, g_A0);
    cudaGetSymbolAddress(&pA1, g_A1);
    __nv_bfloat16* bufs[2] = {(__nv_bfloat16*)pA0, (__nv_bfloat16*)pA1};

    split_x_kernel<<<1024, 256>>>((const float4*)d_in[0]);

    for (int l = 0; l < 4; l++) {
        const float* W  = (const float*)d_in[1 + l*4 + 0];
        const float* b  = (const float*)d_in[1 + l*4 + 1];
        const float* M  = (const float*)d_in[1 + l*4 + 2];
        const float* mb = (const float*)d_in[1 + l*4 + 3];

        clear_kernel<<<1, 1024>>>();
        hist_kernel<<<1024, 256>>>((const float4*)M);
        scan_kernel<<<1, 1024>>>();
        gather_kernel<<<1024, 256>>>((const float4*)M);
        select_kernel<<<1, 1024, SEL_SMEM>>>();
        biasmask_kernel<<<16, 256>>>(b, mb);
        maskconv_kernel<<<1024, 256>>>((const float4*)W, (const float4*)M);

        dim3 gt(DIM/TN, DIM/TM);   // tcgen05 path grid
        dim3 gf(DIM/FN, DIM/FM);   // fallback path grid
        const __nv_bfloat16* Ain = bufs[l & 1];
        if (l == 3) {
            gemm_tc<true><<<gt, 256, TC_SMEM>>>(Ain, nullptr, (float*)d_out);
            gemm_fb<true><<<gf, 512, FB_SMEM>>>(Ain, nullptr, (float*)d_out);
        } else {
            unsigned short* Aout = (unsigned short*)bufs[(l+1) & 1];
            gemm_tc<false><<<gt, 256, TC_SMEM>>>(Ain, Aout, nullptr);
            gemm_fb<false><<<gf, 512, FB_SMEM>>>(Ain, Aout, nullptr);
        }
    }
}

// round 6
// speedup vs baseline: 1.0152x; 1.0152x over previous
#include <cuda_runtime.h>
#include <cuda_bf16.h>
#include <cstdint>

#define DIM      4096
#define NUMEL    (DIM*DIM)
#define KTOT     8388608u
#define KB_TOT   2048
#define NBINS    8192
#define CAP      12288
#define SEL_SMEM  (CAP*8 + 4096*4)

#if defined(__CUDA_ARCH_FEAT_SM103_ALL) || defined(__CUDA_ARCH_FEAT_SM100_ALL)
#define HAS_TC 1
#else
#define HAS_TC 0
#endif

// ---- tcgen05 path config (dormant unless toolchain targets compute_103a) ----
#define TM       128
#define TN       256
#define NSTAGE_T 192
#define NBUF_T   3
#define A_BYTES  (TM*128)
#define STG_T    (A_BYTES + TN*128)
#define TC_SMEM  (2048 + NBUF_T*STG_T)

// ---- fallback path config: 256x128 tile, K=64/stage, 4 bufs, 1 sync/stage ----
#define FM       256
#define FN       128
#define FKS      64
#define NSTAGE_F 192
#define FA_SZ    (FM*128)          // 32768
#define FB_SZ    (FN*128)          // 16384
#define FS_SZ    (FA_SZ+FB_SZ)     // 49152
#define FB_SMEM  (1024 + 4*FS_SZ)  // 197632

static constexpr uint32_t IDESC =
    (1u<<4) | (1u<<7) | (1u<<10) | ((TN/8)<<17) | ((TM/16)<<24);
static constexpr uint64_t DESC_BASE =
    (uint64_t(2)<<61) | (uint64_t(1)<<46) | (uint64_t(64)<<32) | (uint64_t(1)<<16);
#define SWZ(off) ((off) ^ (((off)>>3)&0x70))
#define MKDESC(a) (DESC_BASE | ((uint64_t)((a)>>4) & 0x3FFF))
// SW128 addressing for 128-byte rows: row r, 16B-chunk c (0..7)
#define SOFF(r,c) ((uint32_t)((r)*128 + (((c) ^ ((r)&7))*16)))

__device__ __nv_bfloat16 g_A0[(size_t)DIM*8192];
__device__ __nv_bfloat16 g_A1[(size_t)DIM*8192];
__device__ __nv_bfloat16 g_Wm[(size_t)DIM*8192];
__device__ unsigned int g_hist[NBINS];
__device__ int   g_binstar, g_cbefore, g_cand_cnt;
__device__ float g_cand_val[CAP];
__device__ int   g_cand_idx[CAP];
__device__ float g_tval;
__device__ int   g_tidx;
__device__ float g_bm[DIM];

__device__ __forceinline__ uint32_t smem_u32(const void* p) {
    uint32_t a;
    asm("{ .reg .u64 t; cvta.to.shared.u64 t, %1; cvt.u32.u64 %0, t; }" : "=r"(a) : "l"(p));
    return a;
}
__device__ __forceinline__ void cp16(uint32_t dst, const void* src) {
    asm volatile("cp.async.cg.shared.global [%0], [%1], 16;" :: "r"(dst), "l"(src));
}
#define CP_COMMIT() asm volatile("cp.async.commit_group;" ::: "memory")
#define CP_WAIT(n)  asm volatile("cp.async.wait_group %0;" :: "n"(n) : "memory")

__device__ __forceinline__ int qval(float v) {
    int q = (int)(v * 33554432.0f);
    return q < 0 ? 0 : (q > 33554431 ? 33554431 : q);
}
__device__ __forceinline__ void split_bf16(float v, unsigned short& h, unsigned short& l) {
    __nv_bfloat16 hb = __float2bfloat16(v);
    __nv_bfloat16 lb = __float2bfloat16(v - __bfloat162float(hb));
    h = __bfloat16_as_ushort(hb); l = __bfloat16_as_ushort(lb);
}
// inclusive-scan helper: returns exclusive prefix of val across 1024-thread block
__device__ __forceinline__ unsigned int block_excl_scan(unsigned int val, unsigned int* wsum) {
    int lane = threadIdx.x & 31, warp = threadIdx.x >> 5;
    unsigned int v = val;
    #pragma unroll
    for (int o = 1; o < 32; o <<= 1) {
        unsigned int n = __shfl_up_sync(0xFFFFFFFFu, v, o);
        if (lane >= o) v += n;
    }
    if (lane == 31) wsum[warp] = v;
    __syncthreads();
    if (warp == 0) {
        unsigned int w = wsum[lane];
        #pragma unroll
        for (int o = 1; o < 32; o <<= 1) {
            unsigned int n = __shfl_up_sync(0xFFFFFFFFu, w, o);
            if (lane >= o) w += n;
        }
        wsum[lane] = w;
    }
    __syncthreads();
    return (warp ? wsum[warp-1] : 0u) + v - val;
}

// ---------------- masking pipeline ----------------
__global__ void clear_kernel() {
    for (int i = threadIdx.x; i < NBINS; i += 1024) g_hist[i] = 0;
    if (threadIdx.x == 0) g_cand_cnt = 0;
}

__global__ void hist_kernel(const float4* __restrict__ M4) {
    __shared__ unsigned int h[NBINS];
    for (int i = threadIdx.x; i < NBINS; i += 256) h[i] = 0;
    __syncthreads();
    int stride = gridDim.x * blockDim.x;
    for (int i = blockIdx.x*blockDim.x + threadIdx.x; i < NUMEL/4; i += stride) {
        float4 v = M4[i];
        atomicAdd(&h[qval(v.x)>>12], 1u); atomicAdd(&h[qval(v.y)>>12], 1u);
        atomicAdd(&h[qval(v.z)>>12], 1u); atomicAdd(&h[qval(v.w)>>12], 1u);
    }
    __syncthreads();
    for (int i = threadIdx.x; i < NBINS; i += 256)
        if (h[i]) atomicAdd(&g_hist[i], h[i]);
}

__global__ void scan_kernel() {
    __shared__ unsigned int wsum[32];
    int t = threadIdx.x;
    unsigned int c8[8], s = 0;
    #pragma unroll
    for (int j = 0; j < 8; j++) { c8[j] = g_hist[t*8+j]; s += c8[j]; }
    unsigned int run = block_excl_scan(s, wsum);
    #pragma unroll
    for (int j = 0; j < 8; j++) {
        unsigned int c = c8[j];
        if (run < KTOT && run + c >= KTOT) { g_binstar = t*8+j; g_cbefore = (int)run; }
        run += c;
    }
}

__global__ void gather_kernel(const float4* __restrict__ M4) {
    int bstar = g_binstar;
    int stride = gridDim.x * blockDim.x;
    for (int i = blockIdx.x*blockDim.x + threadIdx.x; i < NUMEL/4; i += stride) {
        float4 v = M4[i];
        float vv[4] = {v.x, v.y, v.z, v.w};
        #pragma unroll
        for (int j = 0; j < 4; j++)
            if ((qval(vv[j])>>12) == bstar) {
                int p = atomicAdd(&g_cand_cnt, 1);
                if (p < CAP) { g_cand_val[p] = vv[j]; g_cand_idx[p] = i*4+j; }
            }
    }
}

__global__ void select_kernel() {
    extern __shared__ char sm[];
    float* sv = (float*)sm;
    int* si = (int*)(sm + CAP*4);
    unsigned int* sh = (unsigned int*)(sm + CAP*8);
    __shared__ unsigned int wsum[32];
    __shared__ int s_b2, s_need2;
    int t = threadIdx.x;
    int c = g_cand_cnt; if (c > CAP) c = CAP;
    int need = (int)KTOT - g_cbefore;
    for (int i = t; i < c; i += 1024) { sv[i] = g_cand_val[i]; si[i] = g_cand_idx[i]; }
    for (int i = t; i < 4096; i += 1024) sh[i] = 0;
    __syncthreads();
    for (int i = t; i < c; i += 1024) atomicAdd(&sh[qval(sv[i]) & 4095], 1u);
    __syncthreads();
    unsigned int c4[4], s = 0;
    #pragma unroll
    for (int j = 0; j < 4; j++) { c4[j] = sh[t*4+j]; s += c4[j]; }
    unsigned int run = block_excl_scan(s, wsum);
    #pragma unroll
    for (int j = 0; j < 4; j++) {
        unsigned int cc = c4[j];
        if (run < (unsigned)need && run + cc >= (unsigned)need) { s_b2 = t*4+j; s_need2 = need - (int)run; }
        run += cc;
    }
    __syncthreads();
    int b2 = s_b2, need2 = s_need2;
    for (int j = t; j < c; j += 1024) {
        float vj = sv[j];
        if ((qval(vj) & 4095) != b2) continue;
        int ij = si[j], cnt = 0;
        for (int i = 0; i < c; i++) {
            float v = sv[i];
            if ((qval(v) & 4095) != b2) continue;
            cnt += (v < vj) || (v == vj && si[i] < ij);
        }
        if (cnt == need2 - 1) { g_tval = vj; g_tidx = ij; }
    }
}

__global__ void biasmask_kernel(const float* __restrict__ b, const float* __restrict__ mb) {
    __shared__ float svv[DIM];
    int t = threadIdx.x, j = blockIdx.x*256 + t;
    for (int i = t; i < DIM; i += 256) svv[i] = mb[i];
    __syncthreads();
    float vj = svv[j];
    int cnt = 0;
    for (int i = 0; i < DIM; i++) { float v = svv[i]; cnt += (v < vj) || (v == vj && i < j); }
    g_bm[j] = (cnt < KB_TOT) ? 0.0f : b[j];
}

__global__ void maskconv_kernel(const float4* __restrict__ W4, const float4* __restrict__ M4) {
    float tv = g_tval; int ti = g_tidx;
    int stride = gridDim.x * blockDim.x;
    unsigned short* Wo = (unsigned short*)g_Wm;
    for (int i = blockIdx.x*blockDim.x + threadIdx.x; i < NUMEL/4; i += stride) {
        float4 w = W4[i]; float4 m = M4[i];
        float wv[4] = {w.x, w.y, w.z, w.w};
        float mv[4] = {m.x, m.y, m.z, m.w};
        int e0 = i*4;
        unsigned short hh[4], ll[4];
        #pragma unroll
        for (int j = 0; j < 4; j++) {
            bool z = (mv[j] < tv) || (mv[j] == tv && (e0+j) <= ti);
            split_bf16(z ? 0.0f : wv[j], hh[j], ll[j]);
        }
        size_t base = (size_t)(e0>>12)*8192 + (e0 & 4095);
        *(ushort4*)(Wo + base)        = make_ushort4(hh[0],hh[1],hh[2],hh[3]);
        *(ushort4*)(Wo + base + 4096) = make_ushort4(ll[0],ll[1],ll[2],ll[3]);
    }
}

__global__ void split_x_kernel(const float4* __restrict__ x4) {
    int stride = gridDim.x * blockDim.x;
    unsigned short* Ao = (unsigned short*)g_A0;
    for (int i = blockIdx.x*blockDim.x + threadIdx.x; i < NUMEL/4; i += stride) {
        float4 v = x4[i];
        float vv[4] = {v.x, v.y, v.z, v.w};
        unsigned short hh[4], ll[4];
        #pragma unroll
        for (int j = 0; j < 4; j++) split_bf16(vv[j], hh[j], ll[j]);
        int e0 = i*4;
        size_t base = (size_t)(e0>>12)*8192 + (e0 & 4095);
        *(ushort4*)(Ao + base)        = make_ushort4(hh[0],hh[1],hh[2],hh[3]);
        *(ushort4*)(Ao + base + 4096) = make_ushort4(ll[0],ll[1],ll[2],ll[3]);
    }
}

// ---------------- tcgen05 GEMM (sm_103a-only, dormant) ----------------
template <bool FINAL>
__global__ void __launch_bounds__(256, 1) gemm_tc(
    const __nv_bfloat16* __restrict__ A,
    unsigned short* __restrict__ outb, float* __restrict__ outf)
{
#if HAS_TC
    extern __shared__ char smem[];
    uint32_t sb = smem_u32(smem);
    float* sbias = (float*)(smem + 64);
    int tid = threadIdx.x, wid = tid >> 5, lane = tid & 31;
    int tn = blockIdx.x, tm = blockIdx.y;

    if (tid == 0) {
        asm volatile("mbarrier.init.shared.b64 [%0], 1;" :: "r"(sb+16) : "memory");
        asm volatile("mbarrier.init.shared.b64 [%0], 1;" :: "r"(sb+24) : "memory");
        asm volatile("mbarrier.init.shared.b64 [%0], 1;" :: "r"(sb+32) : "memory");
    }
    if (wid == 0) {
        asm volatile("tcgen05.alloc.cta_group::1.sync.aligned.shared::cta.b32 [%0], %1;"
            :: "r"(sb), "r"((uint32_t)TN) : "memory");
        asm volatile("tcgen05.relinquish_alloc_permit.cta_group::1.sync.aligned;");
    }
    sbias[tid] = g_bm[tn*TN + tid];
    __syncthreads();
    uint32_t tbase;
    asm volatile("ld.shared.b32 %0, [%1];" : "=r"(tbase) : "r"(sb));

    const char* Ab = (const char*)A;
    const char* Wb = (const char*)g_Wm;

    #define TLOAD(s) do { \
        int seg_ = (s) >> 6, kk_ = ((s) & 63) << 6; \
        int aoff_ = (seg_ == 1 ? 4096 : 0) + kk_; \
        int boff_ = (seg_ == 2 ? 4096 : 0) + kk_; \
        uint32_t stg_ = sb + 2048 + ((s) % NBUF_T) * STG_T; \
        for (int u = tid; u < 3072; u += 256) { \
            if (u < 1024) { \
                int r_ = u >> 3, c_ = u & 7; \
                uint32_t off_ = (uint32_t)(r_*128 + c_*16); \
                cp16(stg_ + SWZ(off_), Ab + (((size_t)(tm*TM + r_))*8192 + aoff_ + c_*8)*2); \
            } else { \
                int v_ = u - 1024, r_ = v_ >> 3, c_ = v_ & 7; \
                uint32_t off_ = (uint32_t)(r_*128 + c_*16); \
                cp16(stg_ + A_BYTES + SWZ(off_), Wb + (((size_t)(tn*TN + r_))*8192 + boff_ + c_*8)*2); \
            } \
        } \
        CP_COMMIT(); \
    } while (0)

    TLOAD(0); TLOAD(1); TLOAD(2);

    for (int s = 0; s < NSTAGE_T; s++) {
        if (s < NSTAGE_T-2)       { CP_WAIT(2); }
        else if (s == NSTAGE_T-2) { CP_WAIT(1); }
        else                      { CP_WAIT(0); }
        __syncthreads();
        uint32_t ep;
        asm volatile("{\n\t.reg .pred P;\n\telect.sync _|P, 0xFFFFFFFF;\n\tselp.b32 %0,1,0,P;\n\t}" : "=r"(ep));
        if (wid == 0 && ep) {
            asm volatile("fence.proxy.async.shared::cta;" ::: "memory");
            uint32_t stg = sb + 2048 + (s % NBUF_T) * STG_T;
            uint64_t ad = MKDESC(stg), bd = MKDESC(stg + A_BYTES);
            #pragma unroll
            for (int k = 0; k < 4; k++) {
                uint32_t en = ((s | k) != 0);
                asm volatile("{\n\t.reg .pred p;\n\tsetp.ne.u32 p, %5, 0;\n\t"
                    "tcgen05.mma.cta_group::1.kind::f16 [%0], %1, %2, %3, {%4,%4,%4,%4}, p;\n\t}"
                    :: "r"(tbase), "l"(ad + k*2), "l"(bd + k*2), "r"(IDESC), "r"(0u), "r"(en) : "memory");
            }
            asm volatile("tcgen05.commit.cta_group::1.mbarrier::arrive::one.shared::cluster.b64 [%0];"
                :: "r"(sb + 16 + (s % NBUF_T)*8) : "memory");
        }
        if (s + NBUF_T < NSTAGE_T) {
            uint32_t mb = sb + 16 + (s % NBUF_T)*8, par = (uint32_t)((s / NBUF_T) & 1);
            asm volatile("{\n\t.reg .pred P;\n\tWL_%=:\n\t"
                "mbarrier.try_wait.parity.acquire.cta.shared::cta.b64 P, [%0], %1, 0x989680;\n\t"
                "@P bra.uni WD_%=;\n\tbra.uni WL_%=;\n\tWD_%=:\n\t}" :: "r"(mb), "r"(par) : "memory");
            TLOAD(s + NBUF_T);
        }
    }
    {
        uint32_t mb = sb + 16 + ((NSTAGE_T-1) % NBUF_T)*8, par = (uint32_t)(((NSTAGE_T-1) / NBUF_T) & 1);
        asm volatile("{\n\t.reg .pred P;\n\tWL_%=:\n\t"
            "mbarrier.try_wait.parity.acquire.cta.shared::cta.b64 P, [%0], %1, 0x989680;\n\t"
            "@P bra.uni WD_%=;\n\tbra.uni WL_%=;\n\tWD_%=:\n\t}" :: "r"(mb), "r"(par) : "memory");
    }
    __syncthreads();
    asm volatile("tcgen05.fence::after_thread_sync;" ::: "memory");

    if (wid < 4) {
        int m = tm*TM + wid*32 + lane;
        #pragma unroll 1
        for (int g = 0; g < 8; g++) {
            uint32_t r[32];
            asm volatile("tcgen05.ld.sync.aligned.32x32b.x32.b32 "
                "{%0,%1,%2,%3,%4,%5,%6,%7,%8,%9,%10,%11,%12,%13,%14,%15,"
                "%16,%17,%18,%19,%20,%21,%22,%23,%24,%25,%26,%27,%28,%29,%30,%31}, [%32];"
                : "=r"(r[0]),"=r"(r[1]),"=r"(r[2]),"=r"(r[3]),"=r"(r[4]),"=r"(r[5]),"=r"(r[6]),"=r"(r[7]),
                  "=r"(r[8]),"=r"(r[9]),"=r"(r[10]),"=r"(r[11]),"=r"(r[12]),"=r"(r[13]),"=r"(r[14]),"=r"(r[15]),
                  "=r"(r[16]),"=r"(r[17]),"=r"(r[18]),"=r"(r[19]),"=r"(r[20]),"=r"(r[21]),"=r"(r[22]),"=r"(r[23]),
                  "=r"(r[24]),"=r"(r[25]),"=r"(r[26]),"=r"(r[27]),"=r"(r[28]),"=r"(r[29]),"=r"(r[30]),"=r"(r[31])
                : "r"(tbase + g*32));
            asm volatile("tcgen05.wait::ld.sync.aligned;" ::: "memory");
            if (!FINAL) {
                #pragma unroll
                for (int q = 0; q < 8; q++) {
                    unsigned short hh[4], ll[4];
                    #pragma unroll
                    for (int j = 0; j < 4; j++) {
                        float v = __uint_as_float(r[q*4+j]) + sbias[g*32 + q*4 + j];
                        split_bf16(fmaxf(v, 0.0f), hh[j], ll[j]);
                    }
                    size_t base = (size_t)m*8192 + tn*TN + g*32 + q*4;
                    *(ushort4*)(outb + base)        = make_ushort4(hh[0],hh[1],hh[2],hh[3]);
                    *(ushort4*)(outb + base + 4096) = make_ushort4(ll[0],ll[1],ll[2],ll[3]);
                }
            } else {
                #pragma unroll
                for (int q = 0; q < 8; q++) {
                    float4 v;
                    v.x = __uint_as_float(r[q*4+0]) + sbias[g*32+q*4+0];
                    v.y = __uint_as_float(r[q*4+1]) + sbias[g*32+q*4+1];
                    v.z = __uint_as_float(r[q*4+2]) + sbias[g*32+q*4+2];
                    v.w = __uint_as_float(r[q*4+3]) + sbias[g*32+q*4+3];
                    *(float4*)(outf + (size_t)m*4096 + tn*TN + g*32 + q*4) = v;
                }
            }
        }
    }
    __syncthreads();
    if (wid == 0)
        asm volatile("tcgen05.dealloc.cta_group::1.sync.aligned.b32 %0, %1;" :: "r"(tbase), "r"((uint32_t)TN));
#endif
}

// ---------------- fallback GEMM: mma.sync bf16, K=64/stage, 1 sync/stage ----
#define LDSM4(r, a) asm volatile("ldmatrix.sync.aligned.m8n8.x4.shared.b16 {%0,%1,%2,%3}, [%4];" \
    : "=r"((r)[0]),"=r"((r)[1]),"=r"((r)[2]),"=r"((r)[3]) : "r"(a))
#define MMA16816(acc, a, b0, b1) asm volatile( \
    "mma.sync.aligned.m16n8k16.row.col.f32.bf16.bf16.f32 {%0,%1,%2,%3},{%4,%5,%6,%7},{%8,%9},{%0,%1,%2,%3};" \
    : "+f"((acc)[0]),"+f"((acc)[1]),"+f"((acc)[2]),"+f"((acc)[3]) \
    : "r"((a)[0]),"r"((a)[1]),"r"((a)[2]),"r"((a)[3]),"r"(b0),"r"(b1))

template <bool FINAL>
__global__ void __launch_bounds__(512, 1) gemm_fb(
    const __nv_bfloat16* __restrict__ A,
    unsigned short* __restrict__ outb, float* __restrict__ outf)
{
#if !HAS_TC
    extern __shared__ char smem[];
    uint32_t sb = smem_u32(smem);
    float* sbias = (float*)smem;
    int tid = threadIdx.x, wid = tid >> 5, lane = tid & 31;
    int mw = wid >> 2, nw = wid & 3;
    int tn = blockIdx.x, tm = blockIdx.y;
    if (tid < FN) sbias[tid] = g_bm[tn*FN + tid];

    const char* Ab = (const char*)A;
    const char* Wb = (const char*)g_Wm;

    float acc[4][4][4];
    #pragma unroll
    for (int i = 0; i < 4; i++)
        #pragma unroll
        for (int j = 0; j < 4; j++)
            #pragma unroll
            for (int k = 0; k < 4; k++) acc[i][j][k] = 0.f;

    // 3072 cp16 per stage (A: 2048, B: 1024), 512 threads -> 6 iters
    #define FLOAD(s) do { \
        int seg_ = (s) >> 6, kk_ = ((s) & 63) << 6; \
        int aoff_ = (seg_ == 1 ? 4096 : 0) + kk_; \
        int boff_ = (seg_ == 2 ? 4096 : 0) + kk_; \
        uint32_t stg_ = sb + 1024 + ((s) & 3) * FS_SZ; \
        for (int u = tid; u < 3072; u += 512) { \
            if (u < 2048) { int r_ = u >> 3, c_ = u & 7; \
                cp16(stg_ + SOFF(r_, c_), Ab + (((size_t)(tm*FM + r_))*8192 + aoff_ + c_*8)*2); \
            } else { int v_ = u - 2048, r_ = v_ >> 3, c_ = v_ & 7; \
                cp16(stg_ + FA_SZ + SOFF(r_, c_), Wb + (((size_t)(tn*FN + r_))*8192 + boff_ + c_*8)*2); } \
        } \
        CP_COMMIT(); \
    } while (0)

    FLOAD(0); FLOAD(1); FLOAD(2);

    int rA = mw*64 + (lane & 15);
    int rB = nw*32 + (lane & 15);
    int chh = lane >> 4;

    for (int s = 0; s < NSTAGE_F; s++) {
        if (s < NSTAGE_F-2)       { CP_WAIT(2); }
        else if (s == NSTAGE_F-2) { CP_WAIT(1); }
        else                      { CP_WAIT(0); }
        __syncthreads();
        if (s + 3 < NSTAGE_F) FLOAD(s + 3);
        uint32_t astg = sb + 1024 + (s & 3) * FS_SZ;
        uint32_t bstg = astg + FA_SZ;
        #pragma unroll
        for (int ks = 0; ks < 4; ks++) {
            int ch = ks*2 + chh;
            uint32_t a[4][4], b[2][4];
            #pragma unroll
            for (int mt = 0; mt < 4; mt++) LDSM4(a[mt], astg + SOFF(rA + mt*16, ch));
            #pragma unroll
            for (int nt = 0; nt < 2; nt++) LDSM4(b[nt], bstg + SOFF(rB + nt*16, ch));
            #pragma unroll
            for (int mt = 0; mt < 4; mt++)
                #pragma unroll
                for (int nt = 0; nt < 2; nt++)
                    #pragma unroll
                    for (int h = 0; h < 2; h++)
                        MMA16816(acc[mt][nt*2+h], a[mt], b[nt][h], b[nt][h+2]);
        }
    }

    int mwb = tm*FM + mw*64;
    #pragma unroll
    for (int mt = 0; mt < 4; mt++)
        #pragma unroll
        for (int nt = 0; nt < 2; nt++)
            #pragma unroll
            for (int h = 0; h < 2; h++) {
                float* c = acc[mt][nt*2+h];
                int m0 = mwb + mt*16 + (lane >> 2);
                int nl = nw*32 + nt*16 + h*8 + (lane & 3)*2;
                int ng = tn*FN + nl;
                float b0 = sbias[nl], b1 = sbias[nl+1];
                #pragma unroll
                for (int rr = 0; rr < 2; rr++) {
                    int m = m0 + rr*8;
                    float v0 = c[rr*2+0] + b0, v1 = c[rr*2+1] + b1;
                    if (!FINAL) {
                        unsigned short h0, l0, h1, l1;
                        split_bf16(fmaxf(v0, 0.f), h0, l0);
                        split_bf16(fmaxf(v1, 0.f), h1, l1);
                        size_t base = (size_t)m*8192 + ng;
                        *(unsigned int*)(outb + base)        = (unsigned int)h0 | ((unsigned int)h1 << 16);
                        *(unsigned int*)(outb + base + 4096) = (unsigned int)l0 | ((unsigned int)l1 << 16);
                    } else {
                        *(float2*)(outf + (size_t)m*4096 + ng) = make_float2(v0, v1);
                    }
                }
            }
#endif
}

// ---------------- launch ----------------
extern "C" void kernel_launch(void* const* d_in, const int* in_sizes, int n_in,
                              void* d_out, int out_size) {
    (void)in_sizes; (void)n_in; (void)out_size;
    cudaFuncSetAttribute(select_kernel, cudaFuncAttributeMaxDynamicSharedMemorySize, SEL_SMEM);
    cudaFuncSetAttribute(gemm_tc<false>, cudaFuncAttributeMaxDynamicSharedMemorySize, TC_SMEM);
    cudaFuncSetAttribute(gemm_tc<true>,  cudaFuncAttributeMaxDynamicSharedMemorySize, TC_SMEM);
    cudaFuncSetAttribute(gemm_fb<false>, cudaFuncAttributeMaxDynamicSharedMemorySize, FB_SMEM);
    cudaFuncSetAttribute(gemm_fb<true>,  cudaFuncAttributeMaxDynamicSharedMemorySize, FB_SMEM);

    void *pA0, *pA1;
    cudaGetSymbolAddress(&pA0, g_A0);
    cudaGetSymbolAddress(&pA1, g_A1);
    __nv_bfloat16* bufs[2] = {(__nv_bfloat16*)pA0, (__nv_bfloat16*)pA1};

    split_x_kernel<<<1024, 256>>>((const float4*)d_in[0]);

    for (int l = 0; l < 4; l++) {
        const float* W  = (const float*)d_in[1 + l*4 + 0];
        const float* b  = (const float*)d_in[1 + l*4 + 1];
        const float* M  = (const float*)d_in[1 + l*4 + 2];
        const float* mb = (const float*)d_in[1 + l*4 + 3];

        clear_kernel<<<1, 1024>>>();
        hist_kernel<<<1024, 256>>>((const float4*)M);
        scan_kernel<<<1, 1024>>>();
        gather_kernel<<<1024, 256>>>((const float4*)M);
        select_kernel<<<1, 1024, SEL_SMEM>>>();
        biasmask_kernel<<<16, 256>>>(b, mb);
        maskconv_kernel<<<1024, 256>>>((const float4*)W, (const float4*)M);

        dim3 gt(DIM/TN, DIM/TM);
        dim3 gf(DIM/FN, DIM/FM);
        const __nv_bfloat16* Ain = bufs[l & 1];
        if (l == 3) {
            gemm_tc<true><<<gt, 256, TC_SMEM>>>(Ain, nullptr, (float*)d_out);
            gemm_fb<true><<<gf, 512, FB_SMEM>>>(Ain, nullptr, (float*)d_out);
        } else {
            unsigned short* Aout = (unsigned short*)bufs[(l+1) & 1];
            gemm_tc<false><<<gt, 256, TC_SMEM>>>(Ain, Aout, nullptr);
            gemm_fb<false><<<gf, 512, FB_SMEM>>>(Ain, Aout, nullptr);
        }
    }
}